// round 7
// baseline (speedup 1.0000x reference)
#include <cuda_runtime.h>

// Problem constants (fixed shapes from reference)
#define BB 4
#define NN 19
#define HH 512
#define WW 512
#define HWc (HH * WW)          // 262144
#define CC 57
#define PAIRS (BB * NN)        // 76
#define TILES 32
#define NBLOCKS (PAIRS * TILES)             // 2432 worker CTAs (+1 watcher)
#define THREADS 256
#define V_PER_TILE (HWc / 4 / TILES)        // 2048 float4 per tile
#define V_PER_THREAD (V_PER_TILE / THREADS) // 8 float4 per thread per plane

// Per-pair accumulators. Zero at module load; the watcher resets them to zero
// after consuming -> state identical on every graph replay.
__device__ float g_bce[PAIRS];
__device__ float g_l1x[PAIRS];
__device__ float g_l1y[PAIRS];
__device__ float g_cnt[PAIRS];
__device__ unsigned int g_count = 0;

__global__ __launch_bounds__(THREADS, 7) void hm_main_kernel(
    const float* __restrict__ fm, const float* __restrict__ lms,
    float* __restrict__ out)
{
    // ---------------- watcher CTA: finalize ----------------
    if (blockIdx.x == NBLOCKS) {
        const int tid = threadIdx.x;
        if (tid == 0) {
            volatile unsigned int* vc = &g_count;
            while (*vc != (unsigned int)NBLOCKS) __nanosleep(200);
        }
        __syncthreads();
        __threadfence();   // acquire: accumulator REDs visible after count

        float t = 0.0f;
        if (tid < PAIRS) {
            const float vb = __ldcg(&g_bce[tid]);
            const float vx = __ldcg(&g_l1x[tid]);
            const float vy = __ldcg(&g_l1y[tid]);
            const float vn = __ldcg(&g_cnt[tid]);
            t = 2.0f * vb * (1.0f / (float)HWc) + (vx + vy) / vn;
        }
        #pragma unroll
        for (int o = 16; o > 0; o >>= 1)
            t += __shfl_down_sync(0xFFFFFFFFu, t, o);

        __shared__ float s[8];
        const int warp = tid >> 5, lane = tid & 31;
        if (lane == 0) s[warp] = t;
        __syncthreads();
        if (tid == 0) {
            float sum = 0.0f;
            #pragma unroll
            for (int i = 0; i < 8; i++) sum += s[i];
            out[0] = sum / (float)PAIRS;
        }
        // reset state for the next graph replay (end state == initial state)
        if (tid < PAIRS) {
            g_bce[tid] = 0.0f; g_l1x[tid] = 0.0f;
            g_l1y[tid] = 0.0f; g_cnt[tid] = 0.0f;
        }
        if (tid == 0) g_count = 0;
        return;
    }

    // ---------------- worker CTAs ----------------
    const int pair = blockIdx.x / TILES;
    const int tile = blockIdx.x % TILES;
    const int b = pair / NN;
    const int n = pair % NN;

    // landmark -> integer center (matches (lm * [H,W]).astype(int32) truncation)
    const float lx = lms[pair * 2 + 0];
    const float ly = lms[pair * 2 + 1];
    const int x = (int)(lx * (float)HH);
    const int y = (int)(ly * (float)WW);

    const size_t base = ((size_t)(b * CC + n)) * (size_t)HWc;
    const float4* __restrict__ pL = (const float4*)(fm + base);
    const float4* __restrict__ pX = (const float4*)(fm + base + (size_t)NN * HWc);
    const float4* __restrict__ pY = (const float4*)(fm + base + (size_t)(2 * NN) * HWc);

    float bce_lin = 0.0f;   // Sum of (l + |l|)  == 2*max(l,0)
    float bce_log = 0.0f;   // Sum of log(1+exp(-|l|)) via log-of-products
    float bce_sub = 0.0f;   // Sum of l over heat==1 pixels
    float l1x = 0.0f, l1y = 0.0f;
    int cnt = 0;

    const int vbase = tile * V_PER_TILE + threadIdx.x;

    #pragma unroll
    for (int k = 0; k < V_PER_THREAD; k++) {
        const int v = vbase + k * THREADS;
        const float4 L = __ldcs(pL + v);    // logits: always needed (79.6MB stream)

        const int h = v >> 7;           // v / 128 (128 float4 per row)
        const int w = (v & 127) << 2;   // starting column of this float4

        const int di = h - x;
        const int di2 = di * di;
        const int rem = 1600 - di2;     // dj^2 budget for this row

        float Lv[4] = {L.x, L.y, L.z, L.w};

        // softplus sum via log of product: 4 parallel EX2 + product tree + 1 LG2
        float e0, e1, e2, e3;
        {
            const float a0 = fabsf(Lv[0]), a1 = fabsf(Lv[1]);
            const float a2 = fabsf(Lv[2]), a3 = fabsf(Lv[3]);
            bce_lin += (Lv[0] + a0) + (Lv[1] + a1) + (Lv[2] + a2) + (Lv[3] + a3);
            e0 = 1.0f + __expf(-a0);
            e1 = 1.0f + __expf(-a1);
            e2 = 1.0f + __expf(-a2);
            e3 = 1.0f + __expf(-a3);
        }
        bce_log += __logf((e0 * e1) * (e2 * e3));

        // Can any of the 4 lanes be inside the disk? (exact test)
        const int dj0 = w - y;               // lane j has dj = dj0 + j
        const int djc = (dj0 > 0) ? dj0 : ((dj0 + 3 < 0) ? -(dj0 + 3) : 0);
        const bool need = (rem >= 0) && (djc * djc <= rem);

        if (need) {
            // PX/PY loaded only inside (or at the fringe of) the disk: ~2% of px
            const float4 PX = __ldcs(pX + v);
            const float4 PY = __ldcs(pY + v);
            const float offx = -(float)di * (1.0f / 40.0f);
            float PXv[4] = {PX.x, PX.y, PX.z, PX.w};
            float PYv[4] = {PY.x, PY.y, PY.z, PY.w};
            #pragma unroll
            for (int j = 0; j < 4; j++) {
                const int dj = dj0 + j;
                if (dj * dj <= rem) {        // heat == 1
                    bce_sub += Lv[j];
                    const float offy = -(float)dj * (1.0f / 40.0f);
                    l1x += fabsf(PXv[j] - offx);
                    l1y += fabsf(PYv[j] - offy);
                    cnt++;
                }
            }
        }
    }

    // bce = 0.5*sum(l+|l|) + sum(softplus) - sum_heat(l)
    float bce = fmaf(0.5f, bce_lin, bce_log) - bce_sub;

    // block reduction: warp shfl, then cross-warp via smem
    float c = (float)cnt;
    #pragma unroll
    for (int o = 16; o > 0; o >>= 1) {
        bce += __shfl_down_sync(0xFFFFFFFFu, bce, o);
        l1x += __shfl_down_sync(0xFFFFFFFFu, l1x, o);
        l1y += __shfl_down_sync(0xFFFFFFFFu, l1y, o);
        c   += __shfl_down_sync(0xFFFFFFFFu, c, o);
    }

    __shared__ float s0[8], s1[8], s2[8], s3[8];
    const int warp = threadIdx.x >> 5;
    const int lane = threadIdx.x & 31;
    if (lane == 0) { s0[warp] = bce; s1[warp] = l1x; s2[warp] = l1y; s3[warp] = c; }
    __syncthreads();
    // warps 1..7 retire here; only thread0 pays the fence.

    if (threadIdx.x == 0) {
        float v0 = 0.f, v1 = 0.f, v2 = 0.f, v3 = 0.f;
        #pragma unroll
        for (int i = 0; i < 8; i++) {
            v0 += s0[i]; v1 += s1[i]; v2 += s2[i]; v3 += s3[i];
        }
        // fire-and-forget REDG accumulation (results unused -> no round trip)
        atomicAdd(&g_bce[pair], v0);
        atomicAdd(&g_l1x[pair], v1);
        atomicAdd(&g_l1y[pair], v2);
        atomicAdd(&g_cnt[pair], v3);
        __threadfence();              // order data REDs before the count RED
        atomicAdd(&g_count, 1u);      // fire-and-forget
    }
}

extern "C" void kernel_launch(void* const* d_in, const int* in_sizes, int n_in,
                              void* d_out, int out_size)
{
    const float* fm  = (const float*)d_in[0];   // feature_maps (4,57,512,512) f32
    const float* lms = (const float*)d_in[1];   // landmarks (4,19,2) f32
    float* out = (float*)d_out;

    hm_main_kernel<<<NBLOCKS + 1, THREADS>>>(fm, lms, out);
}